// round 1
// baseline (speedup 1.0000x reference)
#include <cuda_runtime.h>

#define NB    4096
#define NTOK  49
#define DIM   192
#define HEADS 6
#define HD    32
#define NWIN  64
#define C3    576
#define NTHREADS 384

typedef unsigned long long ull;

// ---------------- device scratch (no allocations allowed) ----------------
__device__ float g_wt[DIM * C3];                 // qkv_w transposed: [k][col]
__device__ float g_pt[DIM * DIM];                // proj_w transposed: [k][e]
__device__ float g_bias[HEADS * NTOK * NTOK];    // bias gathered: [h][i][j]

// ---------------- packed f32x2 helpers ----------------
__device__ __forceinline__ ull fma2(ull a, ull b, ull c) {
    ull d;
    asm("fma.rn.f32x2 %0, %1, %2, %3;" : "=l"(d) : "l"(a), "l"(b), "l"(c));
    return d;
}
__device__ __forceinline__ ull pack2(float x, float y) {
    ull d;
    asm("mov.b64 %0, {%1, %2};" : "=l"(d) : "f"(x), "f"(y));
    return d;
}

// ---------------- prep: transpose weights + gather bias ----------------
__global__ void prep_kernel(const float* __restrict__ qkv_w,
                            const float* __restrict__ proj_w,
                            const float* __restrict__ bias_table,
                            const int*   __restrict__ rel_index) {
    int tid = blockIdx.x * blockDim.x + threadIdx.x;
    int stride = gridDim.x * blockDim.x;
    for (int i = tid; i < DIM * C3; i += stride) {
        int k = i / C3, c = i - k * C3;
        g_wt[i] = qkv_w[c * DIM + k];
    }
    for (int i = tid; i < DIM * DIM; i += stride) {
        int k = i / DIM, e = i - k * DIM;
        g_pt[i] = proj_w[e * DIM + k];
    }
    for (int i = tid; i < HEADS * NTOK * NTOK; i += stride) {
        int h = i / (NTOK * NTOK), r = i - h * (NTOK * NTOK);
        g_bias[i] = bias_table[rel_index[r] * HEADS + h];
    }
}

// ---------------- fused window attention ----------------
// smem layout (floats):
//   [0, 28224)          qkv_s : [49][576]  (q | k | v per token row)
//   [28224, 42630)      attn_s: [6][49][49]  (also x staging [49][192] in phase 0/1)
//   [42630, 53382)      o_s   : [49][192] (+pad to 56 rows for unguarded reads)
#define ATTN_OFF 28224
#define O_OFF    42630
#define SMEM_FLOATS 53382

__global__ __launch_bounds__(NTHREADS, 1)
void win_attn_kernel(const float* __restrict__ x,
                     const float* __restrict__ mask,
                     const float* __restrict__ qkv_b,
                     const float* __restrict__ proj_b,
                     float* __restrict__ out) {
    extern __shared__ float smem[];
    float* qkv_s  = smem;
    float* attn_s = smem + ATTN_OFF;
    float* o_s    = smem + O_OFF;

    const int b   = blockIdx.x;
    const int tid = threadIdx.x;
    const int rg  = tid / 48;   // 0..7 row group
    const int cs  = tid % 48;   // 0..47 column slot

    // ---- phase 0: stage x[b] into smem (attn region doubles as x staging) ----
    {
        const float4* xsrc = (const float4*)(x + (size_t)b * (NTOK * DIM));
        float4* xdst = (float4*)attn_s;
        #pragma unroll
        for (int i = tid; i < (NTOK * DIM) / 4; i += NTHREADS) xdst[i] = xsrc[i];
    }
    __syncthreads();

    // ---- phase 1: qkv = x @ qkv_w^T + qkv_b  -> qkv_s[49][576] ----
    {
        ull binit[6];
        #pragma unroll
        for (int j = 0; j < 6; j++)
            binit[j] = *(const ull*)&qkv_b[2 * cs + 96 * j];
        ull acc[7][6];
        #pragma unroll
        for (int t = 0; t < 7; t++)
            #pragma unroll
            for (int j = 0; j < 6; j++) acc[t][j] = binit[j];

        #pragma unroll 2
        for (int k = 0; k < DIM; k++) {
            const ull* wrow = (const ull*)(g_wt + k * C3);
            ull w[6];
            #pragma unroll
            for (int j = 0; j < 6; j++) w[j] = wrow[cs + 48 * j];
            #pragma unroll
            for (int t = 0; t < 7; t++) {
                float xv = attn_s[(rg + 8 * t) * DIM + k];  // safe: reads within staged region
                ull x2 = pack2(xv, xv);
                #pragma unroll
                for (int j = 0; j < 6; j++) acc[t][j] = fma2(x2, w[j], acc[t][j]);
            }
        }
        #pragma unroll
        for (int t = 0; t < 7; t++) {
            int r = rg + 8 * t;
            if (r < NTOK) {
                #pragma unroll
                for (int j = 0; j < 6; j++)
                    *(ull*)&qkv_s[r * C3 + 2 * cs + 96 * j] = acc[t][j];
            }
        }
    }
    __syncthreads();

    // ---- phase 2: attn[h][i][j] = scale*(q_i . k_j) + bias + mask ----
    {
        const float scale = 0.17677669529663687f;  // 32^-0.5
        const int wi = b % NWIN;
        const float* mrow = mask + (size_t)wi * (NTOK * NTOK);
        for (int idx = tid; idx < HEADS * NTOK * NTOK; idx += NTHREADS) {
            int h  = idx / (NTOK * NTOK);
            int r2 = idx - h * (NTOK * NTOK);
            int i  = r2 / NTOK;
            int j  = r2 - i * NTOK;
            const float4* qp = (const float4*)(qkv_s + i * C3 + h * HD);
            const float4* kp = (const float4*)(qkv_s + j * C3 + DIM + h * HD);
            float s = 0.f;
            #pragma unroll
            for (int d = 0; d < 8; d++) {
                float4 qa = qp[d], kb = kp[d];
                s += qa.x * kb.x + qa.y * kb.y + qa.z * kb.z + qa.w * kb.w;
            }
            attn_s[idx] = s * scale + g_bias[idx] + mrow[r2];
        }
    }
    __syncthreads();

    // ---- phase 3: softmax over last dim, in place (one thread per row) ----
    for (int row = tid; row < HEADS * NTOK; row += NTHREADS) {
        float* a = attn_s + row * NTOK;
        float m = a[0];
        #pragma unroll 7
        for (int j = 1; j < NTOK; j++) m = fmaxf(m, a[j]);
        float s = 0.f;
        #pragma unroll 7
        for (int j = 0; j < NTOK; j++) { float e = __expf(a[j] - m); a[j] = e; s += e; }
        float inv = 1.f / s;
        #pragma unroll 7
        for (int j = 0; j < NTOK; j++) a[j] *= inv;
    }
    __syncthreads();

    // ---- phase 4: o[i][c] = sum_j attn[h][i][j] * v[j][c]  (c = h*32+d) ----
    {
        const int c0 = cs * 4;
        const int h  = c0 / HD;
        ull a0[7], a1[7];
        #pragma unroll
        for (int t = 0; t < 7; t++) { a0[t] = 0ULL; a1[t] = 0ULL; }
        for (int j = 0; j < NTOK; j++) {
            const ull* vp = (const ull*)(qkv_s + j * C3 + 2 * DIM + c0);
            ull v01 = vp[0], v23 = vp[1];
            #pragma unroll
            for (int t = 0; t < 7; t++) {
                int i = rg + 8 * t;
                float aij = attn_s[h * (NTOK * NTOK) + i * NTOK + j]; // overruns read junk, discarded
                ull aa = pack2(aij, aij);
                a0[t] = fma2(aa, v01, a0[t]);
                a1[t] = fma2(aa, v23, a1[t]);
            }
        }
        #pragma unroll
        for (int t = 0; t < 7; t++) {
            int i = rg + 8 * t;
            if (i < NTOK) {
                *(ull*)&o_s[i * DIM + c0]     = a0[t];
                *(ull*)&o_s[i * DIM + c0 + 2] = a1[t];
            }
        }
    }
    __syncthreads();

    // ---- phase 5: out = o @ proj_w^T + proj_b ----
    {
        ull acc[7][2];
        ull b0 = *(const ull*)&proj_b[2 * cs];
        ull b1 = *(const ull*)&proj_b[2 * cs + 96];
        #pragma unroll
        for (int t = 0; t < 7; t++) { acc[t][0] = b0; acc[t][1] = b1; }

        #pragma unroll 2
        for (int k = 0; k < DIM; k++) {
            const ull* prow = (const ull*)(g_pt + k * DIM);
            ull w0 = prow[cs], w1 = prow[cs + 48];
            #pragma unroll
            for (int t = 0; t < 7; t++) {
                float ov = o_s[(rg + 8 * t) * DIM + k];  // pad guarantees in-bounds
                ull o2 = pack2(ov, ov);
                acc[t][0] = fma2(o2, w0, acc[t][0]);
                acc[t][1] = fma2(o2, w1, acc[t][1]);
            }
        }
        float* orow = out + (size_t)b * (NTOK * DIM);
        #pragma unroll
        for (int t = 0; t < 7; t++) {
            int r = rg + 8 * t;
            if (r < NTOK) {
                *(ull*)&orow[r * DIM + 2 * cs]      = acc[t][0];
                *(ull*)&orow[r * DIM + 2 * cs + 96] = acc[t][1];
            }
        }
    }
}

extern "C" void kernel_launch(void* const* d_in, const int* in_sizes, int n_in,
                              void* d_out, int out_size) {
    const float* x          = (const float*)d_in[0];
    const float* mask       = (const float*)d_in[1];
    const float* qkv_w      = (const float*)d_in[2];
    const float* qkv_b      = (const float*)d_in[3];
    const float* proj_w     = (const float*)d_in[4];
    const float* proj_b     = (const float*)d_in[5];
    const float* bias_table = (const float*)d_in[6];
    const int*   rel_index  = (const int*)d_in[7];
    float* out = (float*)d_out;

    prep_kernel<<<120, 256>>>(qkv_w, proj_w, bias_table, rel_index);

    cudaFuncSetAttribute(win_attn_kernel,
                         cudaFuncAttributeMaxDynamicSharedMemorySize,
                         SMEM_FLOATS * (int)sizeof(float));
    win_attn_kernel<<<NB, NTHREADS, SMEM_FLOATS * (int)sizeof(float)>>>(
        x, mask, qkv_b, proj_b, out);
}

// round 3
// speedup vs baseline: 1.1822x; 1.1822x over previous
#include <cuda_runtime.h>
#include <cuda_bf16.h>
#include <cstdint>

typedef unsigned long long ull;
typedef uint32_t u32;

#define TOKS 200704          // 4096 windows * 49 tokens (= 1568 * 128)
#define KEXT 576             // extended K: [hi | hi/lo | lo]
#define NWIN 64

// ---------------- device scratch ----------------
__device__ __nv_bfloat16 g_xe[(size_t)TOKS * KEXT];   // x split-packed [t][xh|xh|xl]
__device__ float         g_qkv[(size_t)TOKS * 576];   // qkv fp32
__device__ __nv_bfloat16 g_oe[(size_t)TOKS * KEXT];   // attn out split-packed
__device__ __nv_bfloat16 g_wqe[576 * KEXT];           // qkv_w packed [n][wh|wl|wh]
__device__ __nv_bfloat16 g_wpe[192 * KEXT];           // proj_w packed
__device__ float         g_bias[6 * 49 * 49];         // gathered rel-pos bias

__device__ __forceinline__ u32 smem_u32(const void* p) {
    u32 a;
    asm("{ .reg .u64 t; cvta.to.shared.u64 t, %1; cvt.u32.u64 %0, t; }" : "=r"(a) : "l"(p));
    return a;
}
__device__ __forceinline__ void cp16(u32 saddr, const void* gaddr) {
    asm volatile("cp.async.cg.shared.global [%0], [%1], 16;" :: "r"(saddr), "l"(gaddr));
}
__device__ __forceinline__ void ldm4(u32* r, u32 addr) {
    asm volatile("ldmatrix.sync.aligned.m8n8.x4.shared.b16 {%0,%1,%2,%3}, [%4];"
                 : "=r"(r[0]), "=r"(r[1]), "=r"(r[2]), "=r"(r[3]) : "r"(addr));
}
__device__ __forceinline__ void mma16816(float* d, const u32* a, u32 b0, u32 b1) {
    asm volatile("mma.sync.aligned.m16n8k16.row.col.f32.bf16.bf16.f32 "
                 "{%0,%1,%2,%3}, {%4,%5,%6,%7}, {%8,%9}, {%0,%1,%2,%3};"
                 : "+f"(d[0]), "+f"(d[1]), "+f"(d[2]), "+f"(d[3])
                 : "r"(a[0]), "r"(a[1]), "r"(a[2]), "r"(a[3]), "r"(b0), "r"(b1));
}

// ---------------- prep: split-pack weights + gather bias ----------------
__global__ void prep_kernel(const float* __restrict__ qkv_w, const float* __restrict__ proj_w,
                            const float* __restrict__ bias_table, const int* __restrict__ rel_index) {
    int tid = blockIdx.x * blockDim.x + threadIdx.x;
    int stride = gridDim.x * blockDim.x;
    for (int i = tid; i < 576 * 192; i += stride) {
        int n = i / 192, k = i - n * 192;
        float w = qkv_w[i];
        __nv_bfloat16 h = __float2bfloat16(w);
        __nv_bfloat16 l = __float2bfloat16(w - __bfloat162float(h));
        g_wqe[(size_t)n * KEXT + k] = h;
        g_wqe[(size_t)n * KEXT + 192 + k] = l;
        g_wqe[(size_t)n * KEXT + 384 + k] = h;
    }
    for (int i = tid; i < 192 * 192; i += stride) {
        int n = i / 192, k = i - n * 192;
        float w = proj_w[i];
        __nv_bfloat16 h = __float2bfloat16(w);
        __nv_bfloat16 l = __float2bfloat16(w - __bfloat162float(h));
        g_wpe[(size_t)n * KEXT + k] = h;
        g_wpe[(size_t)n * KEXT + 192 + k] = l;
        g_wpe[(size_t)n * KEXT + 384 + k] = h;
    }
    for (int i = tid; i < 6 * 2401; i += stride) {
        int h = i / 2401, r = i - h * 2401;
        g_bias[i] = bias_table[rel_index[r] * 6 + h];
    }
}

// ---------------- x -> bf16 split-packed ----------------
__global__ void xconv_kernel(const float* __restrict__ x) {
    size_t idx = (size_t)blockIdx.x * 256 + threadIdx.x;
    size_t t = idx / 96;
    int p = (int)(idx - t * 96);
    float2 v = *(const float2*)(x + t * 192 + 2 * p);
    __nv_bfloat16 h0 = __float2bfloat16(v.x), h1 = __float2bfloat16(v.y);
    __nv_bfloat16 l0 = __float2bfloat16(v.x - __bfloat162float(h0));
    __nv_bfloat16 l1 = __float2bfloat16(v.y - __bfloat162float(h1));
    __nv_bfloat162 hp; hp.x = h0; hp.y = h1;
    __nv_bfloat162 lp; lp.x = l0; lp.y = l1;
    size_t base = t * KEXT + 2 * p;
    *(__nv_bfloat162*)(g_xe + base)       = hp;
    *(__nv_bfloat162*)(g_xe + base + 192) = hp;
    *(__nv_bfloat162*)(g_xe + base + 384) = lp;
}

// ---------------- mma.sync GEMM: out[M,N] = A[M,576] @ W[N,576]^T + bias ----------------
// CTA tile 128x64, 8 warps (4x2), warp tile 32x32, K chunk 64, double-buffered cp.async.
// smem: A buf 2 x 16384 B @0, B buf 2 x 8192 B @32768. Total 49152 B.
#define GSMEM 49152

__global__ __launch_bounds__(256, 2)
void gemm_mma(const float* __restrict__ bias, float* __restrict__ out_param, int which) {
    extern __shared__ char sm[];
    const __nv_bfloat16* Ae = which ? g_oe : g_xe;
    const __nv_bfloat16* We = which ? g_wpe : g_wqe;
    float* outp = which ? out_param : g_qkv;
    const int Ncols = which ? 192 : 576;

    const u32 sb = smem_u32(sm);
    const int tid  = threadIdx.x;
    const int lane = tid & 31;
    const int wid  = tid >> 5;
    const int wm   = wid >> 1;        // 0..3
    const int wn   = wid & 1;         // 0..1
    const size_t row0 = (size_t)blockIdx.x * 128;
    const int    n0   = blockIdx.y * 64;

    float acc[2][4][4];
    #pragma unroll
    for (int mt = 0; mt < 2; mt++)
        #pragma unroll
        for (int nt = 0; nt < 4; nt++)
            #pragma unroll
            for (int q = 0; q < 4; q++) acc[mt][nt][q] = 0.f;

    // precomputed per-thread load slots: 6 jobs (1024 A-chunks + 512 B-chunks)
    // job j: j<1024 -> A row=j>>3, c=j&7; else B row=(j-1024)>>3, c=(j-1024)&7
    auto load_chunk = [&](int kc, int buf) {
        const u32 sA = sb + (u32)buf * 16384u;
        const u32 sB = sb + 32768u + (u32)buf * 8192u;
        #pragma unroll
        for (int s = 0; s < 6; s++) {
            int j = tid + s * 256;
            if (j < 1024) {
                int r = j >> 3, c = j & 7;
                u32 saddr = sA + (u32)r * 128u + (u32)((c ^ (r & 7)) << 4);
                cp16(saddr, Ae + (row0 + r) * KEXT + kc * 64 + c * 8);
            } else {
                int jj = j - 1024;
                int r = jj >> 3, c = jj & 7;
                u32 saddr = sB + (u32)r * 128u + (u32)((c ^ (r & 7)) << 4);
                cp16(saddr, We + (size_t)(n0 + r) * KEXT + kc * 64 + c * 8);
            }
        }
        asm volatile("cp.async.commit_group;" ::: "memory");
    };

    load_chunk(0, 0);

    #pragma unroll 1
    for (int kc = 0; kc < 9; kc++) {
        asm volatile("cp.async.wait_group 0;" ::: "memory");
        __syncthreads();
        if (kc < 8) load_chunk(kc + 1, (kc + 1) & 1);

        const u32 sA = sb + (u32)(kc & 1) * 16384u;
        const u32 sB = sb + 32768u + (u32)(kc & 1) * 8192u;

        #pragma unroll
        for (int ks = 0; ks < 4; ks++) {
            u32 afr[2][4], bfr[2][4];
            #pragma unroll
            for (int mt = 0; mt < 2; mt++) {
                int row = wm * 32 + mt * 16 + (lane & 15);
                int c   = ks * 2 + (lane >> 4);
                ldm4(afr[mt], sA + (u32)row * 128u + (u32)((c ^ (row & 7)) << 4));
            }
            #pragma unroll
            for (int np = 0; np < 2; np++) {
                int brow = wn * 32 + np * 16 + (lane & 7) + ((lane >> 4) & 1) * 8;
                int c    = ks * 2 + ((lane >> 3) & 1);
                ldm4(bfr[np], sB + (u32)brow * 128u + (u32)((c ^ (brow & 7)) << 4));
            }
            #pragma unroll
            for (int mt = 0; mt < 2; mt++)
                #pragma unroll
                for (int nt = 0; nt < 4; nt++)
                    mma16816(acc[mt][nt], afr[mt], bfr[nt >> 1][(nt & 1) * 2], bfr[nt >> 1][(nt & 1) * 2 + 1]);
        }
        __syncthreads();
    }

    // epilogue: C frag rows = t/4 (+8), cols = 2*(t%4)+{0,1}
    const int tr = lane >> 2, tc = (lane & 3) * 2;
    #pragma unroll
    for (int mt = 0; mt < 2; mt++) {
        #pragma unroll
        for (int nt = 0; nt < 4; nt++) {
            int col = n0 + wn * 32 + nt * 8 + tc;
            float b0 = bias[col], b1 = bias[col + 1];
            size_t r_lo = row0 + wm * 32 + mt * 16 + tr;
            float2 v0; v0.x = acc[mt][nt][0] + b0; v0.y = acc[mt][nt][1] + b1;
            float2 v1; v1.x = acc[mt][nt][2] + b0; v1.y = acc[mt][nt][3] + b1;
            *(float2*)(outp + r_lo * Ncols + col)       = v0;
            *(float2*)(outp + (r_lo + 8) * Ncols + col) = v1;
        }
    }
}

// ---------------- per-window attention (fp32), 2 CTAs/window by head-half ----------------
#define AK_OFF  4704
#define AV_OFF  9408
#define AAT_OFF 14112
#define ATT_SMEM (21315 * 4)

__global__ __launch_bounds__(256, 2)
void attn_kernel(const float* __restrict__ mask) {
    extern __shared__ float s[];
    const int tid = threadIdx.x;
    const int win = blockIdx.x >> 1, hb = blockIdx.x & 1;
    const float scale = 0.17677669529663687f;
    const size_t tok0 = (size_t)win * 49;

    for (int idx = tid; idx < 3 * 49 * 24; idx += 256) {
        int sec = idx / (49 * 24), r = idx - sec * 49 * 24, t = r / 24, c4 = r - t * 24;
        float4 v = *(const float4*)(g_qkv + (tok0 + t) * 576 + sec * 192 + hb * 96 + c4 * 4);
        if (sec == 0) { v.x *= scale; v.y *= scale; v.z *= scale; v.w *= scale; }
        *(float4*)(s + sec * 4704 + t * 96 + c4 * 4) = v;
    }
    __syncthreads();

    const int wsel = (win & (NWIN - 1)) * 2401;
    for (int idx = tid; idx < 3 * 2401; idx += 256) {
        int h = idx / 2401, r2 = idx - h * 2401, i = r2 / 49, j = r2 - i * 49;
        const float4* qp = (const float4*)(s + i * 96 + h * 32);
        const float4* kp = (const float4*)(s + AK_OFF + j * 96 + h * 32);
        float acc = 0.f;
        #pragma unroll
        for (int d = 0; d < 8; d++) {
            float4 a = qp[d], bq = kp[d];
            acc += a.x * bq.x + a.y * bq.y + a.z * bq.z + a.w * bq.w;
        }
        s[AAT_OFF + idx] = acc + g_bias[(hb * 3 + h) * 2401 + r2] + mask[wsel + r2];
    }
    __syncthreads();

    if (tid < 147) {
        float* a = s + AAT_OFF + tid * 49;
        float m = a[0];
        #pragma unroll 7
        for (int j = 1; j < 49; j++) m = fmaxf(m, a[j]);
        float sum = 0.f;
        #pragma unroll 7
        for (int j = 0; j < 49; j++) { float e = __expf(a[j] - m); a[j] = e; sum += e; }
        float inv = 1.f / sum;
        #pragma unroll 7
        for (int j = 0; j < 49; j++) a[j] *= inv;
    }
    __syncthreads();

    for (int idx = tid; idx < 49 * 48; idx += 256) {
        int i = idx / 48, cp = idx - i * 48, c = cp * 2, h = c >> 5;
        const float* ar = s + AAT_OFF + h * 2401 + i * 49;
        const float* vp = s + AV_OFF + c;
        float a0 = 0.f, a1 = 0.f;
        #pragma unroll 7
        for (int j = 0; j < 49; j++) {
            float a = ar[j];
            float2 vv = *(const float2*)(vp + j * 96);
            a0 += a * vv.x; a1 += a * vv.y;
        }
        __nv_bfloat16 h0 = __float2bfloat16(a0), h1 = __float2bfloat16(a1);
        __nv_bfloat16 l0 = __float2bfloat16(a0 - __bfloat162float(h0));
        __nv_bfloat16 l1 = __float2bfloat16(a1 - __bfloat162float(h1));
        __nv_bfloat162 hp; hp.x = h0; hp.y = h1;
        __nv_bfloat162 lp; lp.x = l0; lp.y = l1;
        size_t base = (tok0 + i) * KEXT + hb * 96 + c;
        *(__nv_bfloat162*)(g_oe + base)       = hp;
        *(__nv_bfloat162*)(g_oe + base + 192) = hp;
        *(__nv_bfloat162*)(g_oe + base + 384) = lp;
    }
}

// ---------------- launch ----------------
extern "C" void kernel_launch(void* const* d_in, const int* in_sizes, int n_in,
                              void* d_out, int out_size) {
    const float* x          = (const float*)d_in[0];
    const float* mask       = (const float*)d_in[1];
    const float* qkv_w      = (const float*)d_in[2];
    const float* qkv_b      = (const float*)d_in[3];
    const float* proj_w     = (const float*)d_in[4];
    const float* proj_b     = (const float*)d_in[5];
    const float* bias_table = (const float*)d_in[6];
    const int*   rel_index  = (const int*)d_in[7];
    float* out = (float*)d_out;

    prep_kernel<<<120, 256>>>(qkv_w, proj_w, bias_table, rel_index);
    xconv_kernel<<<(TOKS * 96) / 256, 256>>>(x);

    cudaFuncSetAttribute(attn_kernel, cudaFuncAttributeMaxDynamicSharedMemorySize, ATT_SMEM);

    dim3 gq(TOKS / 128, 9);
    gemm_mma<<<gq, 256, GSMEM>>>(qkv_b, nullptr, 0);            // QKV: N=576
    attn_kernel<<<2 * (TOKS / 49), 256, ATT_SMEM>>>(mask);      // 8192 CTAs
    dim3 gp(TOKS / 128, 3);
    gemm_mma<<<gp, 256, GSMEM>>>(proj_b, out, 1);               // proj: N=192
}

// round 5
// speedup vs baseline: 2.5125x; 2.1253x over previous
#include <cuda_runtime.h>
#include <cuda_bf16.h>
#include <cstdint>

typedef unsigned long long ull;
typedef uint32_t u32;

#define TOKS 200704          // 4096 windows * 49 tokens (= 1568 * 128)
#define NWIN 64

// ---------------- device scratch ----------------
__device__ __nv_bfloat16 g_xe[(size_t)TOKS * 384];    // x split [t][hi(192)|lo(192)]
__device__ float         g_qkv[(size_t)TOKS * 576];   // qkv fp32
__device__ __nv_bfloat16 g_oe[(size_t)TOKS * 384];    // attn out split [hi|lo]
__device__ __nv_bfloat16 g_wqe[576 * 576];            // qkv_w packed [n][wh|wl|wh]
__device__ __nv_bfloat16 g_wpe[192 * 576];            // proj_w packed
__device__ float         g_bm[64 * 6 * 49 * 56];      // bias+mask combined, j padded to 56

__device__ __forceinline__ u32 smem_u32(const void* p) {
    u32 a;
    asm("{ .reg .u64 t; cvta.to.shared.u64 t, %1; cvt.u32.u64 %0, t; }" : "=r"(a) : "l"(p));
    return a;
}
__device__ __forceinline__ void cp16(u32 saddr, const void* gaddr) {
    asm volatile("cp.async.cg.shared.global [%0], [%1], 16;" :: "r"(saddr), "l"(gaddr));
}
__device__ __forceinline__ void ldm4(u32* r, u32 addr) {
    asm volatile("ldmatrix.sync.aligned.m8n8.x4.shared.b16 {%0,%1,%2,%3}, [%4];"
                 : "=r"(r[0]), "=r"(r[1]), "=r"(r[2]), "=r"(r[3]) : "r"(addr));
}
__device__ __forceinline__ void mma16816(float* d, const u32* a, u32 b0, u32 b1) {
    asm volatile("mma.sync.aligned.m16n8k16.row.col.f32.bf16.bf16.f32 "
                 "{%0,%1,%2,%3}, {%4,%5,%6,%7}, {%8,%9}, {%0,%1,%2,%3};"
                 : "+f"(d[0]), "+f"(d[1]), "+f"(d[2]), "+f"(d[3])
                 : "r"(a[0]), "r"(a[1]), "r"(a[2]), "r"(a[3]), "r"(b0), "r"(b1));
}
__device__ __forceinline__ ull fma2(ull a, ull b, ull c) {
    ull d; asm("fma.rn.f32x2 %0, %1, %2, %3;" : "=l"(d) : "l"(a), "l"(b), "l"(c)); return d;
}
__device__ __forceinline__ ull add2(ull a, ull b) {
    ull d; asm("add.rn.f32x2 %0, %1, %2;" : "=l"(d) : "l"(a), "l"(b)); return d;
}
__device__ __forceinline__ ull pack2(float x, float y) {
    ull d; asm("mov.b64 %0, {%1, %2};" : "=l"(d) : "f"(x), "f"(y)); return d;
}
__device__ __forceinline__ float2 unp2(ull a) {
    float2 r; asm("mov.b64 {%0, %1}, %2;" : "=f"(r.x), "=f"(r.y) : "l"(a)); return r;
}

// ---------------- prep: split-pack weights + combine bias/mask ----------------
__global__ void prep_kernel(const float* __restrict__ qkv_w, const float* __restrict__ proj_w,
                            const float* __restrict__ bias_table, const int* __restrict__ rel_index,
                            const float* __restrict__ mask) {
    int tid = blockIdx.x * blockDim.x + threadIdx.x;
    int stride = gridDim.x * blockDim.x;
    for (int i = tid; i < 576 * 192; i += stride) {
        int n = i / 192, k = i - n * 192;
        float w = qkv_w[i];
        __nv_bfloat16 h = __float2bfloat16(w);
        __nv_bfloat16 l = __float2bfloat16(w - __bfloat162float(h));
        g_wqe[(size_t)n * 576 + k]       = h;
        g_wqe[(size_t)n * 576 + 192 + k] = l;
        g_wqe[(size_t)n * 576 + 384 + k] = h;
    }
    for (int i = tid; i < 192 * 192; i += stride) {
        int n = i / 192, k = i - n * 192;
        float w = proj_w[i];
        __nv_bfloat16 h = __float2bfloat16(w);
        __nv_bfloat16 l = __float2bfloat16(w - __bfloat162float(h));
        g_wpe[(size_t)n * 576 + k]       = h;
        g_wpe[(size_t)n * 576 + 192 + k] = l;
        g_wpe[(size_t)n * 576 + 384 + k] = h;
    }
    for (int i = tid; i < 64 * 6 * 49 * 56; i += stride) {
        int j = i % 56; int rest = i / 56;
        int ir = rest % 49; rest /= 49;
        int hh = rest % 6; int wm = rest / 6;
        float v = 0.f;
        if (j < 49)
            v = bias_table[rel_index[ir * 49 + j] * 6 + hh] + mask[wm * 2401 + ir * 49 + j];
        g_bm[i] = v;
    }
}

// ---------------- x -> bf16 split [hi|lo] (384 wide) ----------------
__global__ void xconv_kernel(const float* __restrict__ x) {
    size_t idx = (size_t)blockIdx.x * 256 + threadIdx.x;
    size_t t = idx / 96;
    int p = (int)(idx - t * 96);
    float2 v = *(const float2*)(x + t * 192 + 2 * p);
    __nv_bfloat16 h0 = __float2bfloat16(v.x), h1 = __float2bfloat16(v.y);
    __nv_bfloat16 l0 = __float2bfloat16(v.x - __bfloat162float(h0));
    __nv_bfloat16 l1 = __float2bfloat16(v.y - __bfloat162float(h1));
    __nv_bfloat162 hp; hp.x = h0; hp.y = h1;
    __nv_bfloat162 lp; lp.x = l0; lp.y = l1;
    size_t base = t * 384 + 2 * p;
    *(__nv_bfloat162*)(g_xe + base)       = hp;
    *(__nv_bfloat162*)(g_xe + base + 192) = lp;
}

// ---------------- mma.sync GEMM, 3-stage cp.async pipeline ----------------
// CTA 128x64, 8 warps (4x2), warp 32x32, K-chunk 64 of Kext=576.
// Activations phys 384 wide: hi chunks re-read for ext segments.
#define GSMEM 73728

__global__ __launch_bounds__(256, 2)
void gemm_mma(const float* __restrict__ bias, float* __restrict__ out_param, int which) {
    extern __shared__ char sm[];
    const __nv_bfloat16* Ae = which ? g_oe : g_xe;
    const __nv_bfloat16* We = which ? g_wpe : g_wqe;
    float* outp = which ? out_param : g_qkv;
    const int Ncols = which ? 192 : 576;

    const u32 sb = smem_u32(sm);
    const int tid  = threadIdx.x;
    const int lane = tid & 31;
    const int wid  = tid >> 5;
    const int wm   = wid >> 1;
    const int wn   = wid & 1;
    const size_t row0 = (size_t)blockIdx.x * 128;
    const int    n0   = blockIdx.y * 64;

    float acc[2][4][4];
    #pragma unroll
    for (int mt = 0; mt < 2; mt++)
        #pragma unroll
        for (int nt = 0; nt < 4; nt++)
            #pragma unroll
            for (int q = 0; q < 4; q++) acc[mt][nt][q] = 0.f;

    auto load_chunk = [&](int kc, int buf) {
        int aoff = (kc < 3) ? kc * 64 : (kc < 6 ? (kc - 3) * 64 : (kc - 6) * 64 + 192);
        const u32 sA = sb + (u32)buf * 16384u;
        const u32 sB = sb + 49152u + (u32)buf * 8192u;
        #pragma unroll
        for (int s = 0; s < 6; s++) {
            int j = tid + s * 256;
            if (j < 1024) {
                int r = j >> 3, c = j & 7;
                u32 saddr = sA + (u32)r * 128u + (u32)((c ^ (r & 7)) << 4);
                cp16(saddr, Ae + (row0 + r) * 384 + aoff + c * 8);
            } else {
                int jj = j - 1024;
                int r = jj >> 3, c = jj & 7;
                u32 saddr = sB + (u32)r * 128u + (u32)((c ^ (r & 7)) << 4);
                cp16(saddr, We + (size_t)(n0 + r) * 576 + kc * 64 + c * 8);
            }
        }
        asm volatile("cp.async.commit_group;" ::: "memory");
    };

    load_chunk(0, 0);
    load_chunk(1, 1);

    #pragma unroll 1
    for (int kc = 0; kc < 9; kc++) {
        // chunk kc must be COMPLETE: after it, at most (min(8,kc+1)-kc) groups were
        // committed. For kc<8 one younger group may stay in flight; for kc==8 none.
        if (kc < 8) asm volatile("cp.async.wait_group 1;" ::: "memory");
        else        asm volatile("cp.async.wait_group 0;" ::: "memory");
        __syncthreads();
        if (kc + 2 < 9) load_chunk(kc + 2, (kc + 2) % 3);

        const int buf = kc % 3;
        const u32 sA = sb + (u32)buf * 16384u;
        const u32 sB = sb + 49152u + (u32)buf * 8192u;

        #pragma unroll
        for (int ks = 0; ks < 4; ks++) {
            u32 afr[2][4], bfr[2][4];
            #pragma unroll
            for (int mt = 0; mt < 2; mt++) {
                int row = wm * 32 + mt * 16 + (lane & 15);
                int c   = ks * 2 + (lane >> 4);
                ldm4(afr[mt], sA + (u32)row * 128u + (u32)((c ^ (row & 7)) << 4));
            }
            #pragma unroll
            for (int np = 0; np < 2; np++) {
                int brow = wn * 32 + np * 16 + (lane & 7) + ((lane >> 4) & 1) * 8;
                int c    = ks * 2 + ((lane >> 3) & 1);
                ldm4(bfr[np], sB + (u32)brow * 128u + (u32)((c ^ (brow & 7)) << 4));
            }
            #pragma unroll
            for (int mt = 0; mt < 2; mt++)
                #pragma unroll
                for (int nt = 0; nt < 4; nt++)
                    mma16816(acc[mt][nt], afr[mt], bfr[nt >> 1][(nt & 1) * 2], bfr[nt >> 1][(nt & 1) * 2 + 1]);
        }
        __syncthreads();
    }

    const int tr = lane >> 2, tc = (lane & 3) * 2;
    #pragma unroll
    for (int mt = 0; mt < 2; mt++) {
        #pragma unroll
        for (int nt = 0; nt < 4; nt++) {
            int col = n0 + wn * 32 + nt * 8 + tc;
            float b0 = bias[col], b1 = bias[col + 1];
            size_t r_lo = row0 + wm * 32 + mt * 16 + tr;
            float2 v0; v0.x = acc[mt][nt][0] + b0; v0.y = acc[mt][nt][1] + b1;
            float2 v1; v1.x = acc[mt][nt][2] + b0; v1.y = acc[mt][nt][3] + b1;
            *(float2*)(outp + r_lo * Ncols + col)       = v0;
            *(float2*)(outp + (r_lo + 8) * Ncols + col) = v1;
        }
    }
}

// ---------------- attention: conflict-free f32x2 register-tiled ----------------
// CTA = (window, head-half of 3 heads). 256 threads, 2 CTAs/SM.
// smem (bytes):
//   phase QK:   qd @0 (37632: [3h][49i][32d] dup-pairs), kt @37632 (21760: [96c][56j] + pad)
//               sA @59392 (34104: [3h][49i][58j] scores)
//   phase AV:   pt @0 (33184: [3h][49j][56i] probs + pad), v @33184 (18816: [49j][96c])
#define QD_B 0
#define KT_B 37632
#define SA_B 59392
#define PT_B 0
#define V_B  33184
#define ATT_SMEM 93504

__global__ __launch_bounds__(256, 2)
void attn_kernel() {
    extern __shared__ char sm[];
    ull*   qd = (ull*)(sm + QD_B);
    float* kt = (float*)(sm + KT_B);
    float* sA = (float*)(sm + SA_B);
    float* pt = (float*)(sm + PT_B);
    float* vs = (float*)(sm + V_B);

    const int tid  = threadIdx.x;
    const int lane = tid & 31;
    const int wid  = tid >> 5;
    const int win  = blockIdx.x >> 1, hb = blockIdx.x & 1;
    const int wsel = win & (NWIN - 1);
    const size_t tok0 = (size_t)win * 49;
    const float scale = 0.17677669529663687f;

    // ---- P0: stage q (scaled, duplicated pairs) and k (transposed [c][j]) ----
    for (int idx = tid; idx < 49 * 96; idx += 256) {
        int t = idx / 96, c = idx - t * 96;
        const float* src = g_qkv + (tok0 + t) * 576 + hb * 96 + c;
        float qv = src[0] * scale;
        float kv = src[192];
        qd[((c >> 5) * 49 + t) * 32 + (c & 31)] = pack2(qv, qv);
        kt[c * 56 + t] = kv;
    }
    __syncthreads();

    // ---- P1: QK^T + bias + mask -> sA[h][i][j] ----
    for (int task = wid; task < 21; task += 8) {
        int h = task / 7, i0 = (task - h * 7) * 7;
        ull acc[7];
        #pragma unroll
        for (int ii = 0; ii < 7; ii++) acc[ii] = 0ULL;
        const ull*   qb = qd + (h * 49 + i0) * 32;
        const float* kb = kt + h * 32 * 56 + 2 * lane;
        #pragma unroll 4
        for (int dp = 0; dp < 16; dp++) {
            float2 k0 = *(const float2*)(kb + (2 * dp) * 56);
            float2 k1 = *(const float2*)(kb + (2 * dp + 1) * 56);
            ull k0u = pack2(k0.x, k0.y), k1u = pack2(k1.x, k1.y);
            #pragma unroll
            for (int ii = 0; ii < 7; ii++) {
                ulonglong2 qq = *(const ulonglong2*)(qb + ii * 32 + 2 * dp);
                acc[ii] = fma2(qq.x, k0u, acc[ii]);
                acc[ii] = fma2(qq.y, k1u, acc[ii]);
            }
        }
        if (lane < 25) {
            int j0 = 2 * lane;
            const float* bmrow = g_bm + (size_t)((wsel * 6 + hb * 3 + h) * 49 + i0) * 56 + j0;
            #pragma unroll
            for (int ii = 0; ii < 7; ii++) {
                ull bm2 = *(const ull*)(bmrow + ii * 56);
                *(ull*)(sA + (h * 49 + i0 + ii) * 58 + j0) = add2(acc[ii], bm2);
            }
        }
    }
    __syncthreads();

    // ---- P2: softmax rows (tid<147) + transpose into pt[h][j][i]; warps 5-7 stage v ----
    if (tid < 147) {
        int h = tid / 49, i = tid - h * 49;
        float* row = sA + (h * 49 + i) * 58;
        float m = row[0];
        #pragma unroll 7
        for (int j = 1; j < 49; j++) m = fmaxf(m, row[j]);
        float sum = 0.f;
        #pragma unroll 7
        for (int j = 0; j < 49; j++) { float e = __expf(row[j] - m); row[j] = e; sum += e; }
        float inv = 1.f / sum;
        float* ptb = pt + h * 49 * 56 + i;
        #pragma unroll 7
        for (int j = 0; j < 49; j++) ptb[j * 56] = row[j] * inv;
    } else if (tid >= 160) {
        for (int idx = tid - 160; idx < 49 * 24; idx += 96) {
            int t = idx / 24, c4 = idx - t * 24;
            float4 v = *(const float4*)(g_qkv + (tok0 + t) * 576 + 384 + hb * 96 + c4 * 4);
            *(float4*)(vs + t * 96 + c4 * 4) = v;
        }
    }
    __syncthreads();

    // ---- P3: O = P @ V, split-bf16 out to g_oe ----
    for (int task = wid; task < 21; task += 8) {
        int h = task / 7, i0 = (task - h * 7) * 8;
        ull acc[4] = {0ULL, 0ULL, 0ULL, 0ULL};
        const float* vp = vs + h * 32 + lane;
        const float* pb = pt + h * 49 * 56 + i0;
        #pragma unroll 7
        for (int j = 0; j < 49; j++) {
            float vvv = vp[j * 96];
            ull v2 = pack2(vvv, vvv);
            const float4* pr = (const float4*)(pb + j * 56);
            float4 a = pr[0], b = pr[1];
            acc[0] = fma2(pack2(a.x, a.y), v2, acc[0]);
            acc[1] = fma2(pack2(a.z, a.w), v2, acc[1]);
            acc[2] = fma2(pack2(b.x, b.y), v2, acc[2]);
            acc[3] = fma2(pack2(b.z, b.w), v2, acc[3]);
        }
        int cg = hb * 96 + h * 32 + lane;
        #pragma unroll
        for (int p = 0; p < 4; p++) {
            float2 o = unp2(acc[p]);
            int i = i0 + 2 * p;
            #pragma unroll
            for (int e = 0; e < 2; e++) {
                float ov = e ? o.y : o.x;
                int iv = i + e;
                if (iv < 49) {
                    __nv_bfloat16 hi = __float2bfloat16(ov);
                    __nv_bfloat16 lo = __float2bfloat16(ov - __bfloat162float(hi));
                    size_t base = (tok0 + iv) * 384 + cg;
                    g_oe[base]       = hi;
                    g_oe[base + 192] = lo;
                }
            }
        }
    }
}

// ---------------- launch ----------------
extern "C" void kernel_launch(void* const* d_in, const int* in_sizes, int n_in,
                              void* d_out, int out_size) {
    const float* x          = (const float*)d_in[0];
    const float* mask       = (const float*)d_in[1];
    const float* qkv_w      = (const float*)d_in[2];
    const float* qkv_b      = (const float*)d_in[3];
    const float* proj_w     = (const float*)d_in[4];
    const float* proj_b     = (const float*)d_in[5];
    const float* bias_table = (const float*)d_in[6];
    const int*   rel_index  = (const int*)d_in[7];
    float* out = (float*)d_out;

    prep_kernel<<<120, 256>>>(qkv_w, proj_w, bias_table, rel_index, mask);
    xconv_kernel<<<(TOKS * 96) / 256, 256>>>(x);

    cudaFuncSetAttribute(gemm_mma, cudaFuncAttributeMaxDynamicSharedMemorySize, GSMEM);
    cudaFuncSetAttribute(attn_kernel, cudaFuncAttributeMaxDynamicSharedMemorySize, ATT_SMEM);

    dim3 gq(TOKS / 128, 9);
    gemm_mma<<<gq, 256, GSMEM>>>(qkv_b, nullptr, 0);      // QKV: N=576
    attn_kernel<<<2 * (TOKS / 49), 256, ATT_SMEM>>>();    // 8192 CTAs
    dim3 gp(TOKS / 128, 3);
    gemm_mma<<<gp, 256, GSMEM>>>(proj_b, out, 1);         // proj: N=192
}

// round 6
// speedup vs baseline: 2.9290x; 1.1657x over previous
#include <cuda_runtime.h>
#include <cuda_bf16.h>
#include <cstdint>

typedef unsigned long long ull;
typedef uint32_t u32;

#define TOKS 200704          // 4096 windows * 49 tokens (= 1568 * 128)
#define NWIN 64

// ---------------- device scratch ----------------
__device__ __nv_bfloat16 g_xe[(size_t)TOKS * 384];    // x split [t][hi(192)|lo(192)]
__device__ float         g_qkv[(size_t)TOKS * 576];   // qkv fp32
__device__ __nv_bfloat16 g_oe[(size_t)TOKS * 384];    // attn out split [hi|lo]
__device__ __nv_bfloat16 g_wqe[576 * 576];            // qkv_w packed [n][wh|wl|wh]
__device__ __nv_bfloat16 g_wpe[192 * 576];            // proj_w packed
__device__ float         g_bm[64 * 6 * 49 * 56];      // bias+mask combined, j padded to 56

__device__ __forceinline__ u32 smem_u32(const void* p) {
    u32 a;
    asm("{ .reg .u64 t; cvta.to.shared.u64 t, %1; cvt.u32.u64 %0, t; }" : "=r"(a) : "l"(p));
    return a;
}
__device__ __forceinline__ void cp16(u32 saddr, const void* gaddr) {
    asm volatile("cp.async.cg.shared.global [%0], [%1], 16;" :: "r"(saddr), "l"(gaddr));
}
__device__ __forceinline__ void ldm4(u32* r, u32 addr) {
    asm volatile("ldmatrix.sync.aligned.m8n8.x4.shared.b16 {%0,%1,%2,%3}, [%4];"
                 : "=r"(r[0]), "=r"(r[1]), "=r"(r[2]), "=r"(r[3]) : "r"(addr));
}
__device__ __forceinline__ void mma16816(float* d, const u32* a, u32 b0, u32 b1) {
    asm volatile("mma.sync.aligned.m16n8k16.row.col.f32.bf16.bf16.f32 "
                 "{%0,%1,%2,%3}, {%4,%5,%6,%7}, {%8,%9}, {%0,%1,%2,%3};"
                 : "+f"(d[0]), "+f"(d[1]), "+f"(d[2]), "+f"(d[3])
                 : "r"(a[0]), "r"(a[1]), "r"(a[2]), "r"(a[3]), "r"(b0), "r"(b1));
}
__device__ __forceinline__ ull fma2(ull a, ull b, ull c) {
    ull d; asm("fma.rn.f32x2 %0, %1, %2, %3;" : "=l"(d) : "l"(a), "l"(b), "l"(c)); return d;
}
__device__ __forceinline__ ull add2(ull a, ull b) {
    ull d; asm("add.rn.f32x2 %0, %1, %2;" : "=l"(d) : "l"(a), "l"(b)); return d;
}
__device__ __forceinline__ ull pack2(float x, float y) {
    ull d; asm("mov.b64 %0, {%1, %2};" : "=l"(d) : "f"(x), "f"(y)); return d;
}
__device__ __forceinline__ float2 unp2(ull a) {
    float2 r; asm("mov.b64 {%0, %1}, %2;" : "=f"(r.x), "=f"(r.y) : "l"(a)); return r;
}

// ---------------- prep: split-pack weights + combine bias/mask ----------------
__global__ void prep_kernel(const float* __restrict__ qkv_w, const float* __restrict__ proj_w,
                            const float* __restrict__ bias_table, const int* __restrict__ rel_index,
                            const float* __restrict__ mask) {
    int tid = blockIdx.x * blockDim.x + threadIdx.x;
    int stride = gridDim.x * blockDim.x;
    for (int i = tid; i < 576 * 192; i += stride) {
        int n = i / 192, k = i - n * 192;
        float w = qkv_w[i];
        __nv_bfloat16 h = __float2bfloat16(w);
        __nv_bfloat16 l = __float2bfloat16(w - __bfloat162float(h));
        g_wqe[(size_t)n * 576 + k]       = h;
        g_wqe[(size_t)n * 576 + 192 + k] = l;
        g_wqe[(size_t)n * 576 + 384 + k] = h;
    }
    for (int i = tid; i < 192 * 192; i += stride) {
        int n = i / 192, k = i - n * 192;
        float w = proj_w[i];
        __nv_bfloat16 h = __float2bfloat16(w);
        __nv_bfloat16 l = __float2bfloat16(w - __bfloat162float(h));
        g_wpe[(size_t)n * 576 + k]       = h;
        g_wpe[(size_t)n * 576 + 192 + k] = l;
        g_wpe[(size_t)n * 576 + 384 + k] = h;
    }
    for (int i = tid; i < 64 * 6 * 49 * 56; i += stride) {
        int j = i % 56; int rest = i / 56;
        int ir = rest % 49; rest /= 49;
        int hh = rest % 6; int wm = rest / 6;
        float v = 0.f;
        if (j < 49)
            v = bias_table[rel_index[ir * 49 + j] * 6 + hh] + mask[wm * 2401 + ir * 49 + j];
        g_bm[i] = v;
    }
}

// ---------------- x -> bf16 split [hi|lo] (384 wide) ----------------
__global__ void xconv_kernel(const float* __restrict__ x) {
    size_t idx = (size_t)blockIdx.x * 256 + threadIdx.x;
    size_t t = idx / 96;
    int p = (int)(idx - t * 96);
    float2 v = *(const float2*)(x + t * 192 + 2 * p);
    __nv_bfloat16 h0 = __float2bfloat16(v.x), h1 = __float2bfloat16(v.y);
    __nv_bfloat16 l0 = __float2bfloat16(v.x - __bfloat162float(h0));
    __nv_bfloat16 l1 = __float2bfloat16(v.y - __bfloat162float(h1));
    __nv_bfloat162 hp; hp.x = h0; hp.y = h1;
    __nv_bfloat162 lp; lp.x = l0; lp.y = l1;
    size_t base = t * 384 + 2 * p;
    *(__nv_bfloat162*)(g_xe + base)       = hp;
    *(__nv_bfloat162*)(g_xe + base + 192) = lp;
}

// ---------------- mma.sync GEMM, 3-stage cp.async pipeline ----------------
#define GSMEM 73728

__global__ __launch_bounds__(256, 2)
void gemm_mma(const float* __restrict__ bias, float* __restrict__ out_param, int which) {
    extern __shared__ char sm[];
    const __nv_bfloat16* Ae = which ? g_oe : g_xe;
    const __nv_bfloat16* We = which ? g_wpe : g_wqe;
    float* outp = which ? out_param : g_qkv;
    const int Ncols = which ? 192 : 576;

    const u32 sb = smem_u32(sm);
    const int tid  = threadIdx.x;
    const int lane = tid & 31;
    const int wid  = tid >> 5;
    const int wm   = wid >> 1;
    const int wn   = wid & 1;
    const size_t row0 = (size_t)blockIdx.x * 128;
    const int    n0   = blockIdx.y * 64;

    float acc[2][4][4];
    #pragma unroll
    for (int mt = 0; mt < 2; mt++)
        #pragma unroll
        for (int nt = 0; nt < 4; nt++)
            #pragma unroll
            for (int q = 0; q < 4; q++) acc[mt][nt][q] = 0.f;

    auto load_chunk = [&](int kc, int buf) {
        int aoff = (kc < 3) ? kc * 64 : (kc < 6 ? (kc - 3) * 64 : (kc - 6) * 64 + 192);
        const u32 sA = sb + (u32)buf * 16384u;
        const u32 sB = sb + 49152u + (u32)buf * 8192u;
        #pragma unroll
        for (int s = 0; s < 6; s++) {
            int j = tid + s * 256;
            if (j < 1024) {
                int r = j >> 3, c = j & 7;
                u32 saddr = sA + (u32)r * 128u + (u32)((c ^ (r & 7)) << 4);
                cp16(saddr, Ae + (row0 + r) * 384 + aoff + c * 8);
            } else {
                int jj = j - 1024;
                int r = jj >> 3, c = jj & 7;
                u32 saddr = sB + (u32)r * 128u + (u32)((c ^ (r & 7)) << 4);
                cp16(saddr, We + (size_t)(n0 + r) * 576 + kc * 64 + c * 8);
            }
        }
        asm volatile("cp.async.commit_group;" ::: "memory");
    };

    load_chunk(0, 0);
    load_chunk(1, 1);

    #pragma unroll 1
    for (int kc = 0; kc < 9; kc++) {
        if (kc < 8) asm volatile("cp.async.wait_group 1;" ::: "memory");
        else        asm volatile("cp.async.wait_group 0;" ::: "memory");
        __syncthreads();
        if (kc + 2 < 9) load_chunk(kc + 2, (kc + 2) % 3);

        const int buf = kc % 3;
        const u32 sA = sb + (u32)buf * 16384u;
        const u32 sB = sb + 49152u + (u32)buf * 8192u;

        #pragma unroll
        for (int ks = 0; ks < 4; ks++) {
            u32 afr[2][4], bfr[2][4];
            #pragma unroll
            for (int mt = 0; mt < 2; mt++) {
                int row = wm * 32 + mt * 16 + (lane & 15);
                int c   = ks * 2 + (lane >> 4);
                ldm4(afr[mt], sA + (u32)row * 128u + (u32)((c ^ (row & 7)) << 4));
            }
            #pragma unroll
            for (int np = 0; np < 2; np++) {
                int brow = wn * 32 + np * 16 + (lane & 7) + ((lane >> 4) & 1) * 8;
                int c    = ks * 2 + ((lane >> 3) & 1);
                ldm4(bfr[np], sB + (u32)brow * 128u + (u32)((c ^ (brow & 7)) << 4));
            }
            #pragma unroll
            for (int mt = 0; mt < 2; mt++)
                #pragma unroll
                for (int nt = 0; nt < 4; nt++)
                    mma16816(acc[mt][nt], afr[mt], bfr[nt >> 1][(nt & 1) * 2], bfr[nt >> 1][(nt & 1) * 2 + 1]);
        }
        __syncthreads();
    }

    const int tr = lane >> 2, tc = (lane & 3) * 2;
    #pragma unroll
    for (int mt = 0; mt < 2; mt++) {
        #pragma unroll
        for (int nt = 0; nt < 4; nt++) {
            int col = n0 + wn * 32 + nt * 8 + tc;
            float b0 = bias[col], b1 = bias[col + 1];
            size_t r_lo = row0 + wm * 32 + mt * 16 + tr;
            float2 v0; v0.x = acc[mt][nt][0] + b0; v0.y = acc[mt][nt][1] + b1;
            float2 v1; v1.x = acc[mt][nt][2] + b0; v1.y = acc[mt][nt][3] + b1;
            *(float2*)(outp + r_lo * Ncols + col)       = v0;
            *(float2*)(outp + (r_lo + 8) * Ncols + col) = v1;
        }
    }
}

// ---------------- attention: 384 threads, higher occupancy, fewer wavefronts ----
// smem plan (bytes), phases overlap:
//   P0/P1:  qs @0 (18816: [3h][49i][32d]), kt @18816 (21504: [96c][56j]),
//           sA @51744 (34104: [147 rows][58j])
//   P2/P3:  pt @0 (32928: [3h][49j][56i]), vs @32928 (18816: [49j][96c]),
//           sA @51744 (read in P2)
#define QS_B 0
#define KT_B 18816
#define SA_B 51744
#define PT_B 0
#define VS_B 32928
#define ATT_SMEM 85848

__global__ __launch_bounds__(384, 2)
void attn_kernel() {
    extern __shared__ char sm[];
    float* qs = (float*)(sm + QS_B);
    float* kt = (float*)(sm + KT_B);
    float* sA = (float*)(sm + SA_B);
    float* pt = (float*)(sm + PT_B);
    float* vs = (float*)(sm + VS_B);

    const int tid  = threadIdx.x;
    const int lane = tid & 31;
    const int wid  = tid >> 5;
    const int win  = blockIdx.x >> 1, hb = blockIdx.x & 1;
    const int wsel = win & (NWIN - 1);
    const size_t tok0 = (size_t)win * 49;
    const float scale = 0.17677669529663687f;

    // ---- P0: stage q (scaled) and k (transposed [c][j]) ----
    for (int idx = tid; idx < 49 * 96; idx += 384) {
        int t = idx / 96, c = idx - t * 96;
        const float* src = g_qkv + (tok0 + t) * 576 + hb * 96 + c;
        qs[((c >> 5) * 49 + t) * 32 + (c & 31)] = src[0] * scale;
        kt[c * 56 + t] = src[192];
    }
    __syncthreads();

    // ---- P1: QK^T + bias + mask -> sA[h][i][j], 21 tasks over 12 warps ----
    for (int task = wid; task < 21; task += 12) {
        int h = task / 7, i0 = (task - h * 7) * 7;
        ull acc[7] = {0ULL, 0ULL, 0ULL, 0ULL, 0ULL, 0ULL, 0ULL};
        const float* qb = qs + (h * 49 + i0) * 32;
        const float* kb = kt + h * 32 * 56 + 2 * lane;
        #pragma unroll 2
        for (int dq = 0; dq < 8; dq++) {
            float2 k0 = *(const float2*)(kb + (4 * dq + 0) * 56);
            float2 k1 = *(const float2*)(kb + (4 * dq + 1) * 56);
            float2 k2 = *(const float2*)(kb + (4 * dq + 2) * 56);
            float2 k3 = *(const float2*)(kb + (4 * dq + 3) * 56);
            ull ku0 = pack2(k0.x, k0.y), ku1 = pack2(k1.x, k1.y);
            ull ku2 = pack2(k2.x, k2.y), ku3 = pack2(k3.x, k3.y);
            #pragma unroll
            for (int ii = 0; ii < 7; ii++) {
                float4 qf = *(const float4*)(qb + ii * 32 + 4 * dq);
                acc[ii] = fma2(pack2(qf.x, qf.x), ku0, acc[ii]);
                acc[ii] = fma2(pack2(qf.y, qf.y), ku1, acc[ii]);
                acc[ii] = fma2(pack2(qf.z, qf.z), ku2, acc[ii]);
                acc[ii] = fma2(pack2(qf.w, qf.w), ku3, acc[ii]);
            }
        }
        if (lane < 25) {
            int j0 = 2 * lane;
            const float* bmrow = g_bm + (size_t)((wsel * 6 + hb * 3 + h) * 49 + i0) * 56 + j0;
            #pragma unroll
            for (int ii = 0; ii < 7; ii++) {
                ull bm2 = *(const ull*)(bmrow + ii * 56);
                *(ull*)(sA + (h * 49 + i0 + ii) * 58 + j0) = add2(acc[ii], bm2);
            }
        }
    }
    __syncthreads();

    // ---- P2: softmax (tid<147) + transpose to pt[h][j][i]; warps 6-11 stage v ----
    if (tid < 147) {
        int h = tid / 49, i = tid - h * 49;
        float* row = sA + tid * 58;
        float m = row[0];
        #pragma unroll 7
        for (int j = 1; j < 49; j++) m = fmaxf(m, row[j]);
        float sum = 0.f;
        #pragma unroll 7
        for (int j = 0; j < 49; j++) { float e = __expf(row[j] - m); row[j] = e; sum += e; }
        float inv = 1.f / sum;
        float* ptb = pt + h * 2744 + i;
        #pragma unroll 7
        for (int j = 0; j < 49; j++) ptb[j * 56] = row[j] * inv;
    } else if (tid >= 192) {
        for (int idx = tid - 192; idx < 49 * 24; idx += 192) {
            int t = idx / 24, c4 = idx - t * 24;
            float4 v = *(const float4*)(g_qkv + (tok0 + t) * 576 + 384 + hb * 96 + c4 * 4);
            *(float4*)(vs + t * 96 + c4 * 4) = v;
        }
    }
    __syncthreads();

    // ---- P3: O = P @ V, split-bf16 out to g_oe, 21 tasks over 12 warps ----
    for (int task = wid; task < 21; task += 12) {
        int h = task / 7, i0 = (task - h * 7) * 8;
        ull acc[4] = {0ULL, 0ULL, 0ULL, 0ULL};
        const float* vp = vs + h * 32 + lane;
        const float* pb = pt + h * 2744 + i0;
        #pragma unroll 7
        for (int j = 0; j < 49; j++) {
            float vvv = vp[j * 96];
            ull v2 = pack2(vvv, vvv);
            const float4* pr = (const float4*)(pb + j * 56);
            float4 a = pr[0], b = pr[1];
            acc[0] = fma2(pack2(a.x, a.y), v2, acc[0]);
            acc[1] = fma2(pack2(a.z, a.w), v2, acc[1]);
            acc[2] = fma2(pack2(b.x, b.y), v2, acc[2]);
            acc[3] = fma2(pack2(b.z, b.w), v2, acc[3]);
        }
        int cg = hb * 96 + h * 32 + lane;
        #pragma unroll
        for (int p = 0; p < 4; p++) {
            float2 o = unp2(acc[p]);
            int i = i0 + 2 * p;
            #pragma unroll
            for (int e = 0; e < 2; e++) {
                float ov = e ? o.y : o.x;
                int iv = i + e;
                if (iv < 49) {
                    __nv_bfloat16 hi = __float2bfloat16(ov);
                    __nv_bfloat16 lo = __float2bfloat16(ov - __bfloat162float(hi));
                    size_t base = (tok0 + iv) * 384 + cg;
                    g_oe[base]       = hi;
                    g_oe[base + 192] = lo;
                }
            }
        }
    }
}

// ---------------- launch ----------------
extern "C" void kernel_launch(void* const* d_in, const int* in_sizes, int n_in,
                              void* d_out, int out_size) {
    const float* x          = (const float*)d_in[0];
    const float* mask       = (const float*)d_in[1];
    const float* qkv_w      = (const float*)d_in[2];
    const float* qkv_b      = (const float*)d_in[3];
    const float* proj_w     = (const float*)d_in[4];
    const float* proj_b     = (const float*)d_in[5];
    const float* bias_table = (const float*)d_in[6];
    const int*   rel_index  = (const int*)d_in[7];
    float* out = (float*)d_out;

    prep_kernel<<<120, 256>>>(qkv_w, proj_w, bias_table, rel_index, mask);
    xconv_kernel<<<(TOKS * 96) / 256, 256>>>(x);

    cudaFuncSetAttribute(gemm_mma, cudaFuncAttributeMaxDynamicSharedMemorySize, GSMEM);
    cudaFuncSetAttribute(attn_kernel, cudaFuncAttributeMaxDynamicSharedMemorySize, ATT_SMEM);

    dim3 gq(TOKS / 128, 9);
    gemm_mma<<<gq, 256, GSMEM>>>(qkv_b, nullptr, 0);      // QKV: N=576
    attn_kernel<<<2 * (TOKS / 49), 384, ATT_SMEM>>>();    // 8192 CTAs
    dim3 gp(TOKS / 128, 3);
    gemm_mma<<<gp, 256, GSMEM>>>(proj_b, out, 1);         // proj: N=192
}

// round 7
// speedup vs baseline: 3.1321x; 1.0693x over previous
#include <cuda_runtime.h>
#include <cuda_bf16.h>
#include <cstdint>

typedef unsigned long long ull;
typedef uint32_t u32;

#define TOKS 200704          // 4096 windows * 49 tokens (= 1568 * 128)
#define NWIN 64

// ---------------- device scratch ----------------
__device__ __nv_bfloat16 g_xe[(size_t)TOKS * 384];    // x split [t][hi(192)|lo(192)]
__device__ float         g_qkv[(size_t)TOKS * 576];   // qkv fp32
__device__ __nv_bfloat16 g_oe[(size_t)TOKS * 384];    // attn out split [hi|lo]
__device__ __nv_bfloat16 g_wqe[576 * 576];            // qkv_w packed [n][wh|wl|wh]
__device__ __nv_bfloat16 g_wpe[192 * 576];            // proj_w packed
__device__ float         g_bm[64 * 6 * 49 * 56];      // bias+mask combined, j padded to 56

__device__ __forceinline__ u32 smem_u32(const void* p) {
    u32 a;
    asm("{ .reg .u64 t; cvta.to.shared.u64 t, %1; cvt.u32.u64 %0, t; }" : "=r"(a) : "l"(p));
    return a;
}
__device__ __forceinline__ void cp16(u32 saddr, const void* gaddr) {
    asm volatile("cp.async.cg.shared.global [%0], [%1], 16;" :: "r"(saddr), "l"(gaddr));
}
__device__ __forceinline__ void ldm4(u32* r, u32 addr) {
    asm volatile("ldmatrix.sync.aligned.m8n8.x4.shared.b16 {%0,%1,%2,%3}, [%4];"
                 : "=r"(r[0]), "=r"(r[1]), "=r"(r[2]), "=r"(r[3]) : "r"(addr));
}
__device__ __forceinline__ void mma16816(float* d, const u32* a, u32 b0, u32 b1) {
    asm volatile("mma.sync.aligned.m16n8k16.row.col.f32.bf16.bf16.f32 "
                 "{%0,%1,%2,%3}, {%4,%5,%6,%7}, {%8,%9}, {%0,%1,%2,%3};"
                 : "+f"(d[0]), "+f"(d[1]), "+f"(d[2]), "+f"(d[3])
                 : "r"(a[0]), "r"(a[1]), "r"(a[2]), "r"(a[3]), "r"(b0), "r"(b1));
}
__device__ __forceinline__ ull fma2(ull a, ull b, ull c) {
    ull d; asm("fma.rn.f32x2 %0, %1, %2, %3;" : "=l"(d) : "l"(a), "l"(b), "l"(c)); return d;
}
__device__ __forceinline__ ull add2(ull a, ull b) {
    ull d; asm("add.rn.f32x2 %0, %1, %2;" : "=l"(d) : "l"(a), "l"(b)); return d;
}
__device__ __forceinline__ ull pack2(float x, float y) {
    ull d; asm("mov.b64 %0, {%1, %2};" : "=l"(d) : "f"(x), "f"(y)); return d;
}
__device__ __forceinline__ float2 unp2(ull a) {
    float2 r; asm("mov.b64 {%0, %1}, %2;" : "=f"(r.x), "=f"(r.y) : "l"(a)); return r;
}

// ---------------- prep: split-pack weights + combine bias/mask ----------------
__global__ void prep_kernel(const float* __restrict__ qkv_w, const float* __restrict__ proj_w,
                            const float* __restrict__ bias_table, const int* __restrict__ rel_index,
                            const float* __restrict__ mask) {
    int tid = blockIdx.x * blockDim.x + threadIdx.x;
    int stride = gridDim.x * blockDim.x;
    for (int i = tid; i < 576 * 192; i += stride) {
        int n = i / 192, k = i - n * 192;
        float w = qkv_w[i];
        __nv_bfloat16 h = __float2bfloat16(w);
        __nv_bfloat16 l = __float2bfloat16(w - __bfloat162float(h));
        g_wqe[(size_t)n * 576 + k]       = h;
        g_wqe[(size_t)n * 576 + 192 + k] = l;
        g_wqe[(size_t)n * 576 + 384 + k] = h;
    }
    for (int i = tid; i < 192 * 192; i += stride) {
        int n = i / 192, k = i - n * 192;
        float w = proj_w[i];
        __nv_bfloat16 h = __float2bfloat16(w);
        __nv_bfloat16 l = __float2bfloat16(w - __bfloat162float(h));
        g_wpe[(size_t)n * 576 + k]       = h;
        g_wpe[(size_t)n * 576 + 192 + k] = l;
        g_wpe[(size_t)n * 576 + 384 + k] = h;
    }
    for (int i = tid; i < 64 * 6 * 49 * 56; i += stride) {
        int j = i % 56; int rest = i / 56;
        int ir = rest % 49; rest /= 49;
        int hh = rest % 6; int wm = rest / 6;
        float v = 0.f;
        if (j < 49)
            v = bias_table[rel_index[ir * 49 + j] * 6 + hh] + mask[wm * 2401 + ir * 49 + j];
        g_bm[i] = v;
    }
}

// ---------------- x -> bf16 split [hi|lo] (384 wide) ----------------
__global__ void xconv_kernel(const float* __restrict__ x) {
    size_t idx = (size_t)blockIdx.x * 256 + threadIdx.x;
    size_t t = idx / 96;
    int p = (int)(idx - t * 96);
    float2 v = *(const float2*)(x + t * 192 + 2 * p);
    __nv_bfloat16 h0 = __float2bfloat16(v.x), h1 = __float2bfloat16(v.y);
    __nv_bfloat16 l0 = __float2bfloat16(v.x - __bfloat162float(h0));
    __nv_bfloat16 l1 = __float2bfloat16(v.y - __bfloat162float(h1));
    __nv_bfloat162 hp; hp.x = h0; hp.y = h1;
    __nv_bfloat162 lp; lp.x = l0; lp.y = l1;
    size_t base = t * 384 + 2 * p;
    *(__nv_bfloat162*)(g_xe + base)       = hp;
    *(__nv_bfloat162*)(g_xe + base + 192) = lp;
}

// ---------------- mma.sync GEMM, 3-stage cp.async pipeline ----------------
#define GSMEM 73728

__global__ __launch_bounds__(256, 2)
void gemm_mma(const float* __restrict__ bias, float* __restrict__ out_param, int which) {
    extern __shared__ char sm[];
    const __nv_bfloat16* Ae = which ? g_oe : g_xe;
    const __nv_bfloat16* We = which ? g_wpe : g_wqe;
    float* outp = which ? out_param : g_qkv;
    const int Ncols = which ? 192 : 576;

    const u32 sb = smem_u32(sm);
    const int tid  = threadIdx.x;
    const int lane = tid & 31;
    const int wid  = tid >> 5;
    const int wm   = wid >> 1;
    const int wn   = wid & 1;
    const size_t row0 = (size_t)blockIdx.x * 128;
    const int    n0   = blockIdx.y * 64;

    float acc[2][4][4];
    #pragma unroll
    for (int mt = 0; mt < 2; mt++)
        #pragma unroll
        for (int nt = 0; nt < 4; nt++)
            #pragma unroll
            for (int q = 0; q < 4; q++) acc[mt][nt][q] = 0.f;

    auto load_chunk = [&](int kc, int buf) {
        int aoff = (kc < 3) ? kc * 64 : (kc < 6 ? (kc - 3) * 64 : (kc - 6) * 64 + 192);
        const u32 sA = sb + (u32)buf * 16384u;
        const u32 sB = sb + 49152u + (u32)buf * 8192u;
        #pragma unroll
        for (int s = 0; s < 6; s++) {
            int j = tid + s * 256;
            if (j < 1024) {
                int r = j >> 3, c = j & 7;
                u32 saddr = sA + (u32)r * 128u + (u32)((c ^ (r & 7)) << 4);
                cp16(saddr, Ae + (row0 + r) * 384 + aoff + c * 8);
            } else {
                int jj = j - 1024;
                int r = jj >> 3, c = jj & 7;
                u32 saddr = sB + (u32)r * 128u + (u32)((c ^ (r & 7)) << 4);
                cp16(saddr, We + (size_t)(n0 + r) * 576 + kc * 64 + c * 8);
            }
        }
        asm volatile("cp.async.commit_group;" ::: "memory");
    };

    load_chunk(0, 0);
    load_chunk(1, 1);

    #pragma unroll 1
    for (int kc = 0; kc < 9; kc++) {
        if (kc < 8) asm volatile("cp.async.wait_group 1;" ::: "memory");
        else        asm volatile("cp.async.wait_group 0;" ::: "memory");
        __syncthreads();
        if (kc + 2 < 9) load_chunk(kc + 2, (kc + 2) % 3);

        const int buf = kc % 3;
        const u32 sA = sb + (u32)buf * 16384u;
        const u32 sB = sb + 49152u + (u32)buf * 8192u;

        #pragma unroll
        for (int ks = 0; ks < 4; ks++) {
            u32 afr[2][4], bfr[2][4];
            #pragma unroll
            for (int mt = 0; mt < 2; mt++) {
                int row = wm * 32 + mt * 16 + (lane & 15);
                int c   = ks * 2 + (lane >> 4);
                ldm4(afr[mt], sA + (u32)row * 128u + (u32)((c ^ (row & 7)) << 4));
            }
            #pragma unroll
            for (int np = 0; np < 2; np++) {
                int brow = wn * 32 + np * 16 + (lane & 7) + ((lane >> 4) & 1) * 8;
                int c    = ks * 2 + ((lane >> 3) & 1);
                ldm4(bfr[np], sB + (u32)brow * 128u + (u32)((c ^ (brow & 7)) << 4));
            }
            #pragma unroll
            for (int mt = 0; mt < 2; mt++)
                #pragma unroll
                for (int nt = 0; nt < 4; nt++)
                    mma16816(acc[mt][nt], afr[mt], bfr[nt >> 1][(nt & 1) * 2], bfr[nt >> 1][(nt & 1) * 2 + 1]);
        }
        __syncthreads();
    }

    const int tr = lane >> 2, tc = (lane & 3) * 2;
    #pragma unroll
    for (int mt = 0; mt < 2; mt++) {
        #pragma unroll
        for (int nt = 0; nt < 4; nt++) {
            int col = n0 + wn * 32 + nt * 8 + tc;
            float b0 = bias[col], b1 = bias[col + 1];
            size_t r_lo = row0 + wm * 32 + mt * 16 + tr;
            float2 v0; v0.x = acc[mt][nt][0] + b0; v0.y = acc[mt][nt][1] + b1;
            float2 v1; v1.x = acc[mt][nt][2] + b0; v1.y = acc[mt][nt][3] + b1;
            *(float2*)(outp + r_lo * Ncols + col)       = v0;
            *(float2*)(outp + (r_lo + 8) * Ncols + col) = v1;
        }
    }
}

// ---------------- attention: one CTA per (window, head), 128 threads ----------------
// smem (floats, 7770 total = 31080 B -> 7 CTAs/SM):
//   P0/P1: qs @0    (1568: [49i][32d], q scaled)
//          kt @1568 (1792: [32d][56j] transposed)
//          vs @3360 (1568: [49j][32c])
//          sA @4928 (2842: [49i][58j] scores)
//   P2/P3: pt @0    (2744: [49j][56i] probs — overlaps dead qs/kt)
//          vs, sA still live
#define AQS 0
#define AKT 1568
#define AVS 3360
#define ASA 4928
#define ATT_F 7770

__global__ __launch_bounds__(128, 7)
void attn_kernel() {
    __shared__ float s[ATT_F];
    float* qs = s + AQS;
    float* kt = s + AKT;
    float* vs = s + AVS;
    float* sA = s + ASA;
    float* pt = s;   // overlaps qs/kt after P1

    const int tid  = threadIdx.x;
    const int lane = tid & 31;
    const int wid  = tid >> 5;
    const int h    = blockIdx.x;     // 0..5
    const int win  = blockIdx.y;     // 0..4095
    const int wsel = win & (NWIN - 1);
    const size_t tok0 = (size_t)win * 49;
    const float scale = 0.17677669529663687f;

    // ---- P0: stage q (scaled, [i][32]), k (transposed [d][56j]), v ([j][32]) ----
    for (int idx = tid; idx < 49 * 24; idx += 128) {
        int t = idx / 24, p = idx - t * 24;       // p: 0..7 q, 8..15 k, 16..23 v
        int sec = p >> 3, c4 = p & 7;
        float4 v = *(const float4*)(g_qkv + (tok0 + t) * 576 + sec * 192 + h * 32 + c4 * 4);
        if (sec == 0) {
            v.x *= scale; v.y *= scale; v.z *= scale; v.w *= scale;
            *(float4*)(qs + t * 32 + c4 * 4) = v;
        } else if (sec == 1) {
            int c = c4 * 4;
            kt[(c + 0) * 56 + t] = v.x;
            kt[(c + 1) * 56 + t] = v.y;
            kt[(c + 2) * 56 + t] = v.z;
            kt[(c + 3) * 56 + t] = v.w;
        } else {
            *(float4*)(vs + t * 32 + c4 * 4) = v;
        }
    }
    __syncthreads();

    // ---- P1: scores sA[i][j] = q_i.k_j + bias + mask; 7 tasks of 7 rows / 4 warps ----
    for (int task = wid; task < 7; task += 4) {
        int i0 = task * 7;
        ull acc[7] = {0ULL, 0ULL, 0ULL, 0ULL, 0ULL, 0ULL, 0ULL};
        const float* qb = qs + i0 * 32;
        const float* kb = kt + 2 * lane;
        #pragma unroll 2
        for (int dq = 0; dq < 8; dq++) {
            float2 k0 = *(const float2*)(kb + (4 * dq + 0) * 56);
            float2 k1 = *(const float2*)(kb + (4 * dq + 1) * 56);
            float2 k2 = *(const float2*)(kb + (4 * dq + 2) * 56);
            float2 k3 = *(const float2*)(kb + (4 * dq + 3) * 56);
            ull ku0 = pack2(k0.x, k0.y), ku1 = pack2(k1.x, k1.y);
            ull ku2 = pack2(k2.x, k2.y), ku3 = pack2(k3.x, k3.y);
            #pragma unroll
            for (int ii = 0; ii < 7; ii++) {
                float4 qf = *(const float4*)(qb + ii * 32 + 4 * dq);
                acc[ii] = fma2(pack2(qf.x, qf.x), ku0, acc[ii]);
                acc[ii] = fma2(pack2(qf.y, qf.y), ku1, acc[ii]);
                acc[ii] = fma2(pack2(qf.z, qf.z), ku2, acc[ii]);
                acc[ii] = fma2(pack2(qf.w, qf.w), ku3, acc[ii]);
            }
        }
        if (lane < 25) {
            int j0 = 2 * lane;
            const float* bmrow = g_bm + (size_t)((wsel * 6 + h) * 49 + i0) * 56 + j0;
            #pragma unroll
            for (int ii = 0; ii < 7; ii++) {
                ull bm2 = *(const ull*)(bmrow + ii * 56);
                *(ull*)(sA + (i0 + ii) * 58 + j0) = add2(acc[ii], bm2);
            }
        }
    }
    __syncthreads();

    // ---- P2: softmax rows + transpose into pt[j][56i] ----
    if (tid < 49) {
        float* row = sA + tid * 58;
        float m = row[0];
        #pragma unroll 7
        for (int j = 1; j < 49; j++) m = fmaxf(m, row[j]);
        float sum = 0.f;
        #pragma unroll 7
        for (int j = 0; j < 49; j++) { float e = __expf(row[j] - m); row[j] = e; sum += e; }
        float inv = 1.f / sum;
        float* ptb = pt + tid;
        #pragma unroll 7
        for (int j = 0; j < 49; j++) ptb[j * 56] = row[j] * inv;
    }
    __syncthreads();

    // ---- P3: O = P @ V; 7 tasks of 8 rows / 4 warps; split-bf16 out ----
    for (int task = wid; task < 7; task += 4) {
        int i0 = task * 8;
        ull acc[4] = {0ULL, 0ULL, 0ULL, 0ULL};
        const float* vp = vs + lane;
        const float* pb = pt + i0;
        #pragma unroll 7
        for (int j = 0; j < 49; j++) {
            float vvv = vp[j * 32];
            ull v2 = pack2(vvv, vvv);
            const float4* pr = (const float4*)(pb + j * 56);
            float4 a = pr[0], b = pr[1];
            acc[0] = fma2(pack2(a.x, a.y), v2, acc[0]);
            acc[1] = fma2(pack2(a.z, a.w), v2, acc[1]);
            acc[2] = fma2(pack2(b.x, b.y), v2, acc[2]);
            acc[3] = fma2(pack2(b.z, b.w), v2, acc[3]);
        }
        int cg = h * 32 + lane;
        #pragma unroll
        for (int p = 0; p < 4; p++) {
            float2 o = unp2(acc[p]);
            int i = i0 + 2 * p;
            #pragma unroll
            for (int e = 0; e < 2; e++) {
                float ov = e ? o.y : o.x;
                int iv = i + e;
                if (iv < 49) {
                    __nv_bfloat16 hi = __float2bfloat16(ov);
                    __nv_bfloat16 lo = __float2bfloat16(ov - __bfloat162float(hi));
                    size_t base = (tok0 + iv) * 384 + cg;
                    g_oe[base]       = hi;
                    g_oe[base + 192] = lo;
                }
            }
        }
    }
}

// ---------------- launch ----------------
extern "C" void kernel_launch(void* const* d_in, const int* in_sizes, int n_in,
                              void* d_out, int out_size) {
    const float* x          = (const float*)d_in[0];
    const float* mask       = (const float*)d_in[1];
    const float* qkv_w      = (const float*)d_in[2];
    const float* qkv_b      = (const float*)d_in[3];
    const float* proj_w     = (const float*)d_in[4];
    const float* proj_b     = (const float*)d_in[5];
    const float* bias_table = (const float*)d_in[6];
    const int*   rel_index  = (const int*)d_in[7];
    float* out = (float*)d_out;

    prep_kernel<<<120, 256>>>(qkv_w, proj_w, bias_table, rel_index, mask);
    xconv_kernel<<<(TOKS * 96) / 256, 256>>>(x);

    cudaFuncSetAttribute(gemm_mma, cudaFuncAttributeMaxDynamicSharedMemorySize, GSMEM);

    dim3 gq(TOKS / 128, 9);
    gemm_mma<<<gq, 256, GSMEM>>>(qkv_b, nullptr, 0);   // QKV: N=576
    dim3 ga(6, 4096);
    attn_kernel<<<ga, 128>>>();                        // 24576 CTAs
    dim3 gp(TOKS / 128, 3);
    gemm_mma<<<gp, 256, GSMEM>>>(proj_b, out, 1);      // proj: N=192
}